// round 8
// baseline (speedup 1.0000x reference)
#include <cuda_runtime.h>

// Fixed shapes: B=64, P=68, H=W=64 -> 4352 tiles of 4096 pixels
#define HW       4096
#define NTHREADS 256
#define NWARPS   8
#define EPS      1e-5f
#define LOG2E    1.4426950408889634f
#define LN2      0.6931471805599453f

// Raw MUFU intrinsics (exp2f/log2f are PRECISE libm without -use_fast_math)
__device__ __forceinline__ float ex2(float x) {
    float r; asm("ex2.approx.ftz.f32 %0, %1;" : "=f"(r) : "f"(x)); return r;
}
__device__ __forceinline__ float lg2(float x) {
    float r; asm("lg2.approx.f32 %0, %1;" : "=f"(r) : "f"(x)); return r;
}

// Cross-block accumulator (avoids a separate memset launch in the graph).
// Invariant: zero at kernel entry; the last block restores zero before exit.
__device__ float        g_partial = 0.0f;
__device__ unsigned int g_count   = 0u;

__global__ __launch_bounds__(NTHREADS, 5)
void gauss_kl_kernel(const float* __restrict__ hm,
                     const float* __restrict__ means,
                     const float* __restrict__ cov,
                     float* __restrict__ out,
                     float inv_rows)
{
    const int bp  = blockIdx.x;
    const int tid = threadIdx.x;

    // Per-tile Gaussian parameters
    const float mx  = __ldg(&means[bp * 2 + 0]);
    const float my  = __ldg(&means[bp * 2 + 1]);
    const float s00 = __ldg(&cov[bp * 4 + 0]);
    const float s01 = __ldg(&cov[bp * 4 + 1]);
    const float s10 = __ldg(&cov[bp * 4 + 2]);
    const float s11 = __ldg(&cov[bp * 4 + 3]);
    const float det = fmaf(s00, s11, -s01 * s10) + EPS;
    const float inv_det = LOG2E / det;
    // lp2 = log2(exp(-quad/2)) = Ac*dx^2 + Bc*dx*dy + Cc*dy^2
    const float Ac = -0.5f * s11 * inv_det;
    const float Bc =  0.5f * (s01 + s10) * inv_det;
    const float Cc = -0.5f * s00 * inv_det;

    // Geometry: i4 = tid + 256k -> row = (tid>>4) + 16k, x0 = (tid&15)*4
    const float xm  = (float)((tid & 15) << 2) - mx;
    const float dx0 = xm,        dx1 = xm + 1.0f;
    const float dx2 = xm + 2.0f, dx3 = xm + 3.0f;
    const float dyb = (float)(tid >> 4) - my;

    // Pass 1: e = 2^lp2 (EX2), S = pairwise sum  (no heatmap traffic here)
    float e[16];
    float S = 0.0f;
#pragma unroll
    for (int k = 0; k < 4; k++) {
        const float dy   = dyb + (float)(16 * k);
        const float bdy  = Bc * dy;
        const float cdy2 = (Cc * dy) * dy;
        const float e0 = ex2(fmaf(fmaf(Ac, dx0, bdy), dx0, cdy2));
        const float e1 = ex2(fmaf(fmaf(Ac, dx1, bdy), dx1, cdy2));
        const float e2 = ex2(fmaf(fmaf(Ac, dx2, bdy), dx2, cdy2));
        const float e3 = ex2(fmaf(fmaf(Ac, dx3, bdy), dx3, cdy2));
        e[4*k+0] = e0; e[4*k+1] = e1; e[4*k+2] = e2; e[4*k+3] = e3;
        S += (e0 + e1) + (e2 + e3);
    }

    // Reduce S: warp shfl, lane0 -> smem, ONE barrier, all threads sum partials
    __shared__ float ws[NWARPS];
    __shared__ float wa[NWARPS];
    const int wid = tid >> 5, lid = tid & 31;
#pragma unroll
    for (int o = 16; o > 0; o >>= 1) S += __shfl_xor_sync(0xffffffffu, S, o);
    if (lid == 0) ws[wid] = S;
    __syncthreads();
    const float Sfull = ((ws[0] + ws[1]) + (ws[2] + ws[3]))
                      + ((ws[4] + ws[5]) + (ws[6] + ws[7]));
    const float c = EPS * Sfull;                 // pr + eps = (e + c)/S

    // Pass 2: NOW stream the heatmap (LDG latency hidden under the 16
    // independent e+c -> lg2 MUFU ops), then accumulate KL.
    const float4* hm4 = reinterpret_cast<const float4*>(hm + (size_t)bp * HW);
    float4 h0 = __ldcs(&hm4[tid]);
    float4 h1 = __ldcs(&hm4[tid + NTHREADS]);
    float4 h2 = __ldcs(&hm4[tid + 2 * NTHREADS]);
    float4 h3 = __ldcs(&hm4[tid + 3 * NTHREADS]);

    float lgt[16];
#pragma unroll
    for (int j = 0; j < 16; j++) lgt[j] = lg2(e[j] + c);

    float acc = 0.0f;
#pragma unroll
    for (int k = 0; k < 4; k++) {
        const float4 h = (k == 0) ? h0 : (k == 1) ? h1 : (k == 2) ? h2 : h3;
        acc = fmaf(h.x, lg2(h.x) - lgt[4*k+0], acc);
        acc = fmaf(h.y, lg2(h.y) - lgt[4*k+1], acc);
        acc = fmaf(h.z, lg2(h.z) - lgt[4*k+2], acc);
        acc = fmaf(h.w, lg2(h.w) - lgt[4*k+3], acc);
    }

    // Reduce acc; tid0 adds tile value into device scratch
#pragma unroll
    for (int o = 16; o > 0; o >>= 1) acc += __shfl_xor_sync(0xffffffffu, acc, o);
    if (lid == 0) wa[wid] = acc;
    __syncthreads();
    if (tid == 0) {
        const float v = ((wa[0] + wa[1]) + (wa[2] + wa[3]))
                      + ((wa[4] + wa[5]) + (wa[6] + wa[7]));
        // loss_tile = ln2 * (acc + lg2(S))   [sum(hm) == 1 per tile]
        const float tile = (LN2 * inv_rows) * (v + lg2(Sfull));
        atomicAdd(&g_partial, tile);
        __threadfence();
        const unsigned old = atomicAdd(&g_count, 1u);
        if (old == gridDim.x - 1) {          // last block finalizes
            __threadfence();
            out[0]    = g_partial;
            g_partial = 0.0f;                // restore invariant for next replay
            g_count   = 0u;
        }
    }
}

extern "C" void kernel_launch(void* const* d_in, const int* in_sizes, int n_in,
                              void* d_out, int out_size)
{
    const float* hm    = (const float*)d_in[0];   // [B,P,H,W]
    const float* means = (const float*)d_in[1];   // [B,P,2]
    const float* cov   = (const float*)d_in[2];   // [B,P,4]
    float* out = (float*)d_out;

    const int n_bp = in_sizes[1] / 2;             // 4352

    gauss_kl_kernel<<<n_bp, NTHREADS>>>(hm, means, cov, out, 1.0f / (float)n_bp);
}